// round 14
// baseline (speedup 1.0000x reference)
#include <cuda_runtime.h>

// YOLOv1 loss, GB300 sm_103a — persistent 64-thread blocks, FOUR-stage
// cp.async pipeline with TILE=32: same smem/block (30.7KB -> 7 blocks/SM,
// 14 warps/SM) as the R9 champion, but wait_group(2) keeps TWO tiles
// streaming per block at all times (in-flight bytes/SM ~161KB vs ~54KB).
//
// pred:   (16384, 7, 7, 30) f32   d_in[0]
// target: (16384, 7, 7, 30) f32   d_in[1]
// out:    scalar f32

#define N_BATCH 16384
#define N_CELLS (N_BATCH * 49)            // 802816
#define TPB 64
#define TILE 32                            // cells per tile
#define TILE_FLOATS (TILE * 30)            // 960 floats per tensor per tile
#define VEC4_PER_TENSOR (TILE_FLOATS / 4)  // 240
#define NTILES (N_CELLS / TILE)            // 25088 (exact)
#define GRID (7 * 148)                     // 1036 persistent blocks, 7/SM
#define NSTAGE 4

__device__ double g_acc;
__device__ unsigned int g_count;

__device__ __forceinline__ void cp16(void* smem_dst, const void* gmem_src) {
    unsigned int s = (unsigned int)__cvta_generic_to_shared(smem_dst);
    asm volatile("cp.async.cg.shared.global [%0], [%1], 16;\n"
                 :: "r"(s), "l"(gmem_src) : "memory");
}
__device__ __forceinline__ void cp_commit() {
    asm volatile("cp.async.commit_group;\n" ::: "memory");
}
__device__ __forceinline__ void cp_wait2() {
    asm volatile("cp.async.wait_group 2;\n" ::: "memory");
}
__device__ __forceinline__ void cp_wait1() {
    asm volatile("cp.async.wait_group 1;\n" ::: "memory");
}
__device__ __forceinline__ void cp_wait0() {
    asm volatile("cp.async.wait_group 0;\n" ::: "memory");
}

__global__ void __launch_bounds__(TPB, 7) yolo_loss_kernel(
    const float* __restrict__ pred,
    const float* __restrict__ targ,
    float* __restrict__ out)
{
    __shared__ __align__(16) float sp[NSTAGE][TILE_FLOATS];
    __shared__ __align__(16) float st[NSTAGE][TILE_FLOATS];
    __shared__ float warpsum[TPB / 32];
    __shared__ unsigned int s_ticket;

    const int tid = threadIdx.x;

    // ---- prefetch: tile -> stage buffer (coalesced float4 LDGSTS) ----
    // 240 float4 per tensor split over 64 threads: 1 full round + 56-lane rest.
    auto prefetch = [&](int buf, int tile) {
        const float4* gp = (const float4*)(pred + (size_t)tile * TILE_FLOATS);
        const float4* gt = (const float4*)(targ + (size_t)tile * TILE_FLOATS);
        float4* s4p = (float4*)sp[buf];
        float4* s4t = (float4*)st[buf];
        cp16(s4p + tid, gp + tid);
        cp16(s4t + tid, gt + tid);
        cp16(s4p + tid + TPB, gp + tid + TPB);
        cp16(s4t + tid + TPB, gt + tid + TPB);
        cp16(s4p + tid + 2 * TPB, gp + tid + 2 * TPB);
        cp16(s4t + tid + 2 * TPB, gt + tid + 2 * TPB);
        if (tid < VEC4_PER_TENSOR - 3 * TPB) {     // remaining 48
            cp16(s4p + tid + 3 * TPB, gp + tid + 3 * TPB);
            cp16(s4t + tid + 3 * TPB, gt + tid + 3 * TPB);
        }
    };

    // ---- balanced contiguous chunk for this block ----
    const int b = blockIdx.x;
    const int base = NTILES / GRID;                // 24
    const int rem = NTILES % GRID;                 // 224
    const int cnt = base + (b < rem ? 1 : 0);      // 24 or 25 tiles
    const int tile0 = b * base + (b < rem ? b : rem);

    float acc = 0.0f;

    // ---- prologue: 3 tiles in flight ----
    prefetch(0, tile0);
    cp_commit();
    if (cnt > 1) { prefetch(1, tile0 + 1); cp_commit(); }
    if (cnt > 2) { prefetch(2, tile0 + 2); cp_commit(); }

    for (int k = 0; k < cnt; k++) {
        // retire tile k's group; tiles k+1, k+2 (if any) keep streaming
        const int younger = cnt - 1 - k;
        if (younger >= 2)      cp_wait2();
        else if (younger == 1) cp_wait1();
        else                   cp_wait0();
        __syncthreads();       // async-proxy visibility; protects stage (k+3)&3
                               // (consumed at iteration k-1)

        if (k + 3 < cnt) {
            prefetch((k + 3) & 3, tile0 + k + 3);
            cp_commit();
        }

        // ---- per-cell loss: warp 0 computes (cell = tid), warp 1 loads only ----
        if (tid < TILE) {
            const float* p = sp[k & 3] + tid * 30;
            const float* t = st[k & 3] + tid * 30;

            const float coo = (t[4] > 0.0f) ? 1.0f : 0.0f;
            const float noo = 1.0f - coo;

            float d4 = p[4] - t[4];
            float d9 = p[9] - t[9];
            float loss = 0.5f * noo * (d4 * d4 + d9 * d9);

            float cls = 0.0f;
#pragma unroll
            for (int kk = 10; kk < 30; kk++) {
                float d = p[kk] - t[kk];
                cls += d * d;
            }
            loss += coo * cls;

            // degenerate IoU, matching the reference exactly:
            // inter = 1 iff (rb-lt)<0 in BOTH dims, else 0
            const float t_ltx = t[0] - 0.5f * t[2];
            const float t_lty = t[1] - 0.5f * t[3];
            const float t_rbx = t[0] + 0.5f * t[2];
            const float t_rby = t[1] + 0.5f * t[3];
            const float area2 = (t_rbx - t_ltx) * (t_rby - t_lty);

            float iou[2];
#pragma unroll
            for (int bb = 0; bb < 2; bb++) {
                const float* pb = p + bb * 5;
                float p_ltx = pb[0] - 0.5f * pb[2];
                float p_lty = pb[1] - 0.5f * pb[3];
                float p_rbx = pb[0] + 0.5f * pb[2];
                float p_rby = pb[1] + 0.5f * pb[3];
                float ltx = fmaxf(p_ltx, t_ltx);
                float lty = fmaxf(p_lty, t_lty);
                float rbx = fminf(p_rbx, t_rbx);
                float rby = fminf(p_rby, t_rby);
                float wh0 = (rbx - ltx < 0.0f) ? 1.0f : 0.0f;
                float wh1 = (rby - lty < 0.0f) ? 1.0f : 0.0f;
                float inter = wh0 * wh1;
                float area1 = (p_rbx - p_ltx) * (p_rby - p_lty);
                iou[bb] = inter / (area1 + area2 - inter);
            }
            const int idx = (iou[1] > iou[0]) ? 1 : 0;  // first index on ties
            const float* rp = p + idx * 5;
            const float* rt = t + idx * 5;

            float dc = rp[4] - rt[4];
            loss += coo * dc * dc;

            float dx = rp[0] - rt[0];
            float dy = rp[1] - rt[1];
            float wp2 = (coo > 0.0f) ? rp[2] : 1.0f;
            float wp3 = (coo > 0.0f) ? rp[3] : 1.0f;
            float wt2 = (coo > 0.0f) ? rt[2] : 1.0f;
            float wt3 = (coo > 0.0f) ? rt[3] : 1.0f;
            float dw = sqrtf(wp2) - sqrtf(wt2);
            float dh = sqrtf(wp3) - sqrtf(wt3);
            loss += 5.0f * coo * (dx * dx + dy * dy + dw * dw + dh * dh);

            acc += loss;
        }
        // no end barrier: stage reuse is protected by the next iteration's
        // top barrier (prefetch into a stage happens only after it)
    }

    // ---- block reduction (warp 1 holds acc=0) ----
#pragma unroll
    for (int o = 16; o > 0; o >>= 1)
        acc += __shfl_xor_sync(0xFFFFFFFFu, acc, o);
    if ((tid & 31) == 0)
        warpsum[tid >> 5] = acc;
    __syncthreads();

    if (tid == 0) {
        float s = warpsum[0] + warpsum[1];
        atomicAdd(&g_acc, (double)s * (1.0 / (double)N_BATCH));
        __threadfence();
        s_ticket = atomicAdd(&g_count, 1u);
    }
    __syncthreads();

    // ---- last block publishes scalar and resets state ----
    if (tid == 0 && s_ticket == GRID - 1) {
        double total = atomicAdd(&g_acc, 0.0);
        out[0] = (float)total;
        g_acc = 0.0;
        g_count = 0u;
    }
}

extern "C" void kernel_launch(void* const* d_in, const int* in_sizes, int n_in,
                              void* d_out, int out_size) {
    (void)in_sizes; (void)n_in; (void)out_size;
    const float* pred = (const float*)d_in[0];
    const float* targ = (const float*)d_in[1];
    float* out = (float*)d_out;

    yolo_loss_kernel<<<GRID, TPB>>>(pred, targ, out);
}

// round 15
// speedup vs baseline: 1.0953x; 1.0953x over previous
#include <cuda_runtime.h>

// YOLOv1 loss, GB300 sm_103a — persistent 64-thread blocks, 2-stage pipeline
// with BULK TMA (cp.async.bulk + mbarrier) instead of per-16B LDGSTS.
// Rationale: the kernel must move 81K x 16B/SM; LDGSTS issue cost (~0.5-1.8
// cyc/op at the LSU) consumed most issue slots. One UBLKCP per tensor per
// tile moves 7680B with a single instruction; SM issue pipes freed.
//
// pred:   (16384, 7, 7, 30) f32   d_in[0]
// target: (16384, 7, 7, 30) f32   d_in[1]
// out:    scalar f32
//
// smem/block = 2 stages x 2 tensors x 64 cells x 120B = 30720B -> 7 blocks/SM.

#define N_BATCH 16384
#define N_CELLS (N_BATCH * 49)            // 802816
#define TPB 64
#define TILE 64                            // cells per tile (1 per thread)
#define TILE_FLOATS (TILE * 30)            // 1920 floats per tensor per tile
#define TILE_BYTES (TILE_FLOATS * 4)       // 7680 bytes per tensor per tile
#define NTILES (N_CELLS / TILE)            // 12544 (exact)
#define GRID (7 * 148)                     // 1036 persistent blocks, 7/SM

__device__ double g_acc;
__device__ unsigned int g_count;

__device__ __forceinline__ unsigned int smem_u32(const void* p) {
    return (unsigned int)__cvta_generic_to_shared(p);
}

__device__ __forceinline__ void mbar_init(unsigned int mbar, unsigned int cnt) {
    asm volatile("mbarrier.init.shared.b64 [%0], %1;" :: "r"(mbar), "r"(cnt) : "memory");
}
__device__ __forceinline__ void mbar_expect_tx(unsigned int mbar, unsigned int bytes) {
    asm volatile("mbarrier.arrive.expect_tx.shared.b64 _, [%0], %1;"
                 :: "r"(mbar), "r"(bytes) : "memory");
}
__device__ __forceinline__ void bulk_g2s(unsigned int sdst, const void* gsrc,
                                         unsigned int bytes, unsigned int mbar) {
    asm volatile(
        "cp.async.bulk.shared::cta.global.mbarrier::complete_tx::bytes "
        "[%0], [%1], %2, [%3];"
        :: "r"(sdst), "l"(gsrc), "r"(bytes), "r"(mbar) : "memory");
}
__device__ __forceinline__ void mbar_wait(unsigned int mbar, unsigned int parity) {
    asm volatile(
        "{\n\t"
        ".reg .pred P;\n\t"
        "WAIT_%=:\n\t"
        "mbarrier.try_wait.parity.acquire.cta.shared::cta.b64 P, [%0], %1, 0x989680;\n\t"
        "@P bra.uni DONE_%=;\n\t"
        "bra.uni WAIT_%=;\n\t"
        "DONE_%=:\n\t"
        "}"
        :: "r"(mbar), "r"(parity) : "memory");
}

__global__ void __launch_bounds__(TPB, 7) yolo_loss_kernel(
    const float* __restrict__ pred,
    const float* __restrict__ targ,
    float* __restrict__ out)
{
    __shared__ __align__(16) float sp[2][TILE_FLOATS];
    __shared__ __align__(16) float st[2][TILE_FLOATS];
    __shared__ __align__(8) unsigned long long mbar_full[2];
    __shared__ float warpsum[TPB / 32];
    __shared__ unsigned int s_ticket;

    const int tid = threadIdx.x;

    // ---- balanced contiguous chunk for this block ----
    const int b = blockIdx.x;
    const int base = NTILES / GRID;               // 12
    const int rem = NTILES % GRID;                // 112
    const int cnt = base + (b < rem ? 1 : 0);     // 12 or 13 tiles
    const int tile0 = b * base + (b < rem ? b : rem);

    const unsigned int mb0 = smem_u32(&mbar_full[0]);
    const unsigned int mb1 = smem_u32(&mbar_full[1]);

    // ---- init mbarriers, then issue TMA for tiles 0 and 1 ----
    if (tid == 0) {
        mbar_init(mb0, 1);
        mbar_init(mb1, 1);
    }
    __syncthreads();   // init visible before any complete_tx can arrive

    if (tid == 0) {
        // tile 0 -> stage 0
        mbar_expect_tx(mb0, 2 * TILE_BYTES);
        bulk_g2s(smem_u32(sp[0]), pred + (size_t)tile0 * TILE_FLOATS, TILE_BYTES, mb0);
        bulk_g2s(smem_u32(st[0]), targ + (size_t)tile0 * TILE_FLOATS, TILE_BYTES, mb0);
        if (cnt > 1) {
            // tile 1 -> stage 1
            mbar_expect_tx(mb1, 2 * TILE_BYTES);
            bulk_g2s(smem_u32(sp[1]), pred + (size_t)(tile0 + 1) * TILE_FLOATS, TILE_BYTES, mb1);
            bulk_g2s(smem_u32(st[1]), targ + (size_t)(tile0 + 1) * TILE_FLOATS, TILE_BYTES, mb1);
        }
    }

    float acc = 0.0f;

    for (int k = 0; k < cnt; k++) {
        const int stg = k & 1;
        const unsigned int mb = stg ? mb1 : mb0;
        const unsigned int parity = (k >> 1) & 1;   // flips each reuse of a stage

        mbar_wait(mb, parity);   // tile k landed in stage stg (acquire)

        // ---- per-cell loss (thread tid owns cell tid of tile k) ----
        const float* p = sp[stg] + tid * 30;
        const float* t = st[stg] + tid * 30;

        const float coo = (t[4] > 0.0f) ? 1.0f : 0.0f;
        const float noo = 1.0f - coo;

        float d4 = p[4] - t[4];
        float d9 = p[9] - t[9];
        float loss = 0.5f * noo * (d4 * d4 + d9 * d9);

        float cls = 0.0f;
#pragma unroll
        for (int kk = 10; kk < 30; kk++) {
            float d = p[kk] - t[kk];
            cls += d * d;
        }
        loss += coo * cls;

        // degenerate IoU, matching the reference exactly:
        // inter = 1 iff (rb-lt)<0 in BOTH dims, else 0
        const float t_ltx = t[0] - 0.5f * t[2];
        const float t_lty = t[1] - 0.5f * t[3];
        const float t_rbx = t[0] + 0.5f * t[2];
        const float t_rby = t[1] + 0.5f * t[3];
        const float area2 = (t_rbx - t_ltx) * (t_rby - t_lty);

        float iou[2];
#pragma unroll
        for (int bb = 0; bb < 2; bb++) {
            const float* pb = p + bb * 5;
            float p_ltx = pb[0] - 0.5f * pb[2];
            float p_lty = pb[1] - 0.5f * pb[3];
            float p_rbx = pb[0] + 0.5f * pb[2];
            float p_rby = pb[1] + 0.5f * pb[3];
            float ltx = fmaxf(p_ltx, t_ltx);
            float lty = fmaxf(p_lty, t_lty);
            float rbx = fminf(p_rbx, t_rbx);
            float rby = fminf(p_rby, t_rby);
            float wh0 = (rbx - ltx < 0.0f) ? 1.0f : 0.0f;
            float wh1 = (rby - lty < 0.0f) ? 1.0f : 0.0f;
            float inter = wh0 * wh1;
            float area1 = (p_rbx - p_ltx) * (p_rby - p_lty);
            iou[bb] = inter / (area1 + area2 - inter);
        }
        const int idx = (iou[1] > iou[0]) ? 1 : 0;   // first index on ties
        const float* rp = p + idx * 5;
        const float* rt = t + idx * 5;

        float dc = rp[4] - rt[4];
        loss += coo * dc * dc;

        float dx = rp[0] - rt[0];
        float dy = rp[1] - rt[1];
        float wp2 = (coo > 0.0f) ? rp[2] : 1.0f;
        float wp3 = (coo > 0.0f) ? rp[3] : 1.0f;
        float wt2 = (coo > 0.0f) ? rt[2] : 1.0f;
        float wt3 = (coo > 0.0f) ? rt[3] : 1.0f;
        float dw = sqrtf(wp2) - sqrtf(wt2);
        float dh = sqrtf(wp3) - sqrtf(wt3);
        loss += 5.0f * coo * (dx * dx + dy * dy + dw * dw + dh * dh);

        acc += loss;

        __syncthreads();   // all threads done reading stage stg

        // refill stage stg with tile k+2 (overlaps compute of tile k+1)
        if (tid == 0 && k + 2 < cnt) {
            const int tnext = tile0 + k + 2;
            mbar_expect_tx(mb, 2 * TILE_BYTES);
            bulk_g2s(smem_u32(sp[stg]), pred + (size_t)tnext * TILE_FLOATS, TILE_BYTES, mb);
            bulk_g2s(smem_u32(st[stg]), targ + (size_t)tnext * TILE_FLOATS, TILE_BYTES, mb);
        }
    }

    // ---- block reduction ----
#pragma unroll
    for (int o = 16; o > 0; o >>= 1)
        acc += __shfl_xor_sync(0xFFFFFFFFu, acc, o);
    if ((tid & 31) == 0)
        warpsum[tid >> 5] = acc;
    __syncthreads();

    if (tid == 0) {
        float s = warpsum[0] + warpsum[1];
        atomicAdd(&g_acc, (double)s * (1.0 / (double)N_BATCH));
        __threadfence();
        s_ticket = atomicAdd(&g_count, 1u);
    }
    __syncthreads();

    // ---- last block publishes scalar and resets state ----
    if (tid == 0 && s_ticket == GRID - 1) {
        double total = atomicAdd(&g_acc, 0.0);
        out[0] = (float)total;
        g_acc = 0.0;
        g_count = 0u;
    }
}

extern "C" void kernel_launch(void* const* d_in, const int* in_sizes, int n_in,
                              void* d_out, int out_size) {
    (void)in_sizes; (void)n_in; (void)out_size;
    const float* pred = (const float*)d_in[0];
    const float* targ = (const float*)d_in[1];
    float* out = (float*)d_out;

    yolo_loss_kernel<<<GRID, TPB>>>(pred, targ, out);
}

// round 16
// speedup vs baseline: 1.1033x; 1.0072x over previous
#include <cuda_runtime.h>

// YOLOv1 loss, GB300 sm_103a — R9 champion (persistent 64-thread blocks,
// 2-stage cp.async pipeline, contiguous balanced chunks) + distance-2
// L2 prefetch: while computing tile k (and streaming tile k+1 via cp.async),
// warm L2 for tile k+2 with destination-less prefetch.global.L2.
//
// pred:   (16384, 7, 7, 30) f32   d_in[0]
// target: (16384, 7, 7, 30) f32   d_in[1]
// out:    scalar f32
//
// smem/block = 2 x 2 x 64 x 120B = 30720B -> 7 blocks/SM, 14 warps/SM.

#define N_BATCH 16384
#define N_CELLS (N_BATCH * 49)            // 802816
#define TPB 64
#define TILE 64                            // cells per tile (1 per thread)
#define TILE_FLOATS (TILE * 30)            // 1920 floats per tensor per tile
#define TILE_BYTES (TILE_FLOATS * 4)       // 7680 B per tensor per tile
#define VEC4_PER_TENSOR (TILE_FLOATS / 4)  // 480
#define LINES_PER_TENSOR (TILE_BYTES / 128) // 60
#define NTILES (N_CELLS / TILE)            // 12544 (exact)
#define GRID (7 * 148)                     // 1036 persistent blocks, 7/SM

__device__ double g_acc;
__device__ unsigned int g_count;

__device__ __forceinline__ void cp16(void* smem_dst, const void* gmem_src) {
    unsigned int s = (unsigned int)__cvta_generic_to_shared(smem_dst);
    asm volatile("cp.async.cg.shared.global [%0], [%1], 16;\n"
                 :: "r"(s), "l"(gmem_src) : "memory");
}
__device__ __forceinline__ void cp_commit() {
    asm volatile("cp.async.commit_group;\n" ::: "memory");
}
__device__ __forceinline__ void cp_wait0() {
    asm volatile("cp.async.wait_group 0;\n" ::: "memory");
}
__device__ __forceinline__ void l2_prefetch(const void* g) {
    asm volatile("prefetch.global.L2 [%0];" :: "l"(g));
}

__global__ void __launch_bounds__(TPB, 7) yolo_loss_kernel(
    const float* __restrict__ pred,
    const float* __restrict__ targ,
    float* __restrict__ out)
{
    __shared__ __align__(16) float sp[2][TILE_FLOATS];
    __shared__ __align__(16) float st[2][TILE_FLOATS];
    __shared__ float warpsum[TPB / 32];
    __shared__ unsigned int s_ticket;

    const int tid = threadIdx.x;

    // ---- prefetch: tile -> stage buffer (coalesced float4 LDGSTS) ----
    auto prefetch = [&](int buf, int tile) {
        const float4* gp = (const float4*)(pred + (size_t)tile * TILE_FLOATS);
        const float4* gt = (const float4*)(targ + (size_t)tile * TILE_FLOATS);
        float4* s4p = (float4*)sp[buf];
        float4* s4t = (float4*)st[buf];
#pragma unroll
        for (int i = 0; i < 7; i++) {            // 7*64 = 448 of 480
            cp16(s4p + tid + i * TPB, gp + tid + i * TPB);
            cp16(s4t + tid + i * TPB, gt + tid + i * TPB);
        }
        if (tid < VEC4_PER_TENSOR - 7 * TPB) {   // remaining 32
            cp16(s4p + tid + 7 * TPB, gp + tid + 7 * TPB);
            cp16(s4t + tid + 7 * TPB, gt + tid + 7 * TPB);
        }
    };

    // ---- balanced contiguous chunk for this block ----
    const int b = blockIdx.x;
    const int base = NTILES / GRID;              // 12
    const int rem = NTILES % GRID;               // 112
    const int cnt = base + (b < rem ? 1 : 0);    // 12 or 13 tiles
    int tile = b * base + (b < rem ? b : rem);   // contiguous start

    float acc = 0.0f;
    int cur = 0;

    prefetch(0, tile);
    cp_commit();

    for (int k = 0; k < cnt; k++) {
        cp_wait0();           // this block's pending group (tile k) complete
        __syncthreads();      // async-proxy visibility + all lanes done with
                              // the buffer about to be refilled
        if (k + 1 < cnt) {
            prefetch(cur ^ 1, tile + 1);         // overlap with compute below
            cp_commit();
        }
        if (k + 2 < cnt && tid < LINES_PER_TENSOR) {
            // warm L2 for tile k+2 (no smem/reg destination, no hazards)
            const char* gp2 = (const char*)(pred + (size_t)(tile + 2) * TILE_FLOATS);
            const char* gt2 = (const char*)(targ + (size_t)(tile + 2) * TILE_FLOATS);
            l2_prefetch(gp2 + tid * 128);
            l2_prefetch(gt2 + tid * 128);
        }

        // ---- per-cell loss (thread tid owns cell tid of this tile) ----
        const float* p = sp[cur] + tid * 30;
        const float* t = st[cur] + tid * 30;

        const float coo = (t[4] > 0.0f) ? 1.0f : 0.0f;
        const float noo = 1.0f - coo;

        float d4 = p[4] - t[4];
        float d9 = p[9] - t[9];
        float loss = 0.5f * noo * (d4 * d4 + d9 * d9);

        float cls = 0.0f;
#pragma unroll
        for (int kk = 10; kk < 30; kk++) {
            float d = p[kk] - t[kk];
            cls += d * d;
        }
        loss += coo * cls;

        // degenerate IoU, matching the reference exactly:
        // inter = 1 iff (rb-lt)<0 in BOTH dims, else 0
        const float t_ltx = t[0] - 0.5f * t[2];
        const float t_lty = t[1] - 0.5f * t[3];
        const float t_rbx = t[0] + 0.5f * t[2];
        const float t_rby = t[1] + 0.5f * t[3];
        const float area2 = (t_rbx - t_ltx) * (t_rby - t_lty);

        float iou[2];
#pragma unroll
        for (int bb = 0; bb < 2; bb++) {
            const float* pb = p + bb * 5;
            float p_ltx = pb[0] - 0.5f * pb[2];
            float p_lty = pb[1] - 0.5f * pb[3];
            float p_rbx = pb[0] + 0.5f * pb[2];
            float p_rby = pb[1] + 0.5f * pb[3];
            float ltx = fmaxf(p_ltx, t_ltx);
            float lty = fmaxf(p_lty, t_lty);
            float rbx = fminf(p_rbx, t_rbx);
            float rby = fminf(p_rby, t_rby);
            float wh0 = (rbx - ltx < 0.0f) ? 1.0f : 0.0f;
            float wh1 = (rby - lty < 0.0f) ? 1.0f : 0.0f;
            float inter = wh0 * wh1;
            float area1 = (p_rbx - p_ltx) * (p_rby - p_lty);
            iou[bb] = inter / (area1 + area2 - inter);
        }
        const int idx = (iou[1] > iou[0]) ? 1 : 0;   // first index on ties
        const float* rp = p + idx * 5;
        const float* rt = t + idx * 5;

        float dc = rp[4] - rt[4];
        loss += coo * dc * dc;

        float dx = rp[0] - rt[0];
        float dy = rp[1] - rt[1];
        float wp2 = (coo > 0.0f) ? rp[2] : 1.0f;
        float wp3 = (coo > 0.0f) ? rp[3] : 1.0f;
        float wt2 = (coo > 0.0f) ? rt[2] : 1.0f;
        float wt3 = (coo > 0.0f) ? rt[3] : 1.0f;
        float dw = sqrtf(wp2) - sqrtf(wt2);
        float dh = sqrtf(wp3) - sqrtf(wt3);
        loss += 5.0f * coo * (dx * dx + dy * dy + dw * dw + dh * dh);

        acc += loss;

        cur ^= 1;
        tile += 1;
        // no end barrier: buffer reuse is protected by the next
        // iteration's top barrier (prefetch is issued only after it)
    }

    // ---- block reduction ----
#pragma unroll
    for (int o = 16; o > 0; o >>= 1)
        acc += __shfl_xor_sync(0xFFFFFFFFu, acc, o);
    if ((tid & 31) == 0)
        warpsum[tid >> 5] = acc;
    __syncthreads();

    if (tid == 0) {
        float s = warpsum[0] + warpsum[1];
        atomicAdd(&g_acc, (double)s * (1.0 / (double)N_BATCH));
        __threadfence();
        s_ticket = atomicAdd(&g_count, 1u);
    }
    __syncthreads();

    // ---- last block publishes scalar and resets state ----
    if (tid == 0 && s_ticket == GRID - 1) {
        double total = atomicAdd(&g_acc, 0.0);
        out[0] = (float)total;
        g_acc = 0.0;
        g_count = 0u;
    }
}

extern "C" void kernel_launch(void* const* d_in, const int* in_sizes, int n_in,
                              void* d_out, int out_size) {
    (void)in_sizes; (void)n_in; (void)out_size;
    const float* pred = (const float*)d_in[0];
    const float* targ = (const float*)d_in[1];
    float* out = (float*)d_out;

    yolo_loss_kernel<<<GRID, TPB>>>(pred, targ, out);
}

// round 17
// speedup vs baseline: 1.1723x; 1.0626x over previous
#include <cuda_runtime.h>

// YOLOv1 loss, GB300 sm_103a — R9 champion with TPB=96 (3 warps/block):
// identical tiles, stages, smem (30.7KB -> 7 blocks/SM) and schedule, but
// 21 warps/SM instead of 14 for faster load-issue and deeper latency hiding.
// 480 float4 per tensor per tile = exactly 5 rounds of 96 threads.
//
// pred:   (16384, 7, 7, 30) f32   d_in[0]
// target: (16384, 7, 7, 30) f32   d_in[1]
// out:    scalar f32

#define N_BATCH 16384
#define N_CELLS (N_BATCH * 49)            // 802816
#define TPB 96
#define TILE 64                            // cells per tile
#define TILE_FLOATS (TILE * 30)            // 1920 floats per tensor per tile
#define VEC4_PER_TENSOR (TILE_FLOATS / 4)  // 480 = 5 * 96 exactly
#define NTILES (N_CELLS / TILE)            // 12544 (exact)
#define GRID (7 * 148)                     // 1036 persistent blocks, 7/SM

__device__ double g_acc;
__device__ unsigned int g_count;

__device__ __forceinline__ void cp16(void* smem_dst, const void* gmem_src) {
    unsigned int s = (unsigned int)__cvta_generic_to_shared(smem_dst);
    asm volatile("cp.async.cg.shared.global [%0], [%1], 16;\n"
                 :: "r"(s), "l"(gmem_src) : "memory");
}
__device__ __forceinline__ void cp_commit() {
    asm volatile("cp.async.commit_group;\n" ::: "memory");
}
__device__ __forceinline__ void cp_wait0() {
    asm volatile("cp.async.wait_group 0;\n" ::: "memory");
}

__global__ void __launch_bounds__(TPB, 7) yolo_loss_kernel(
    const float* __restrict__ pred,
    const float* __restrict__ targ,
    float* __restrict__ out)
{
    __shared__ __align__(16) float sp[2][TILE_FLOATS];
    __shared__ __align__(16) float st[2][TILE_FLOATS];
    __shared__ float warpsum[TPB / 32];
    __shared__ unsigned int s_ticket;

    const int tid = threadIdx.x;

    // ---- prefetch: tile -> stage buffer (coalesced float4 LDGSTS),
    //      exactly 5 rounds of 96 threads per tensor ----
    auto prefetch = [&](int buf, int tile) {
        const float4* gp = (const float4*)(pred + (size_t)tile * TILE_FLOATS);
        const float4* gt = (const float4*)(targ + (size_t)tile * TILE_FLOATS);
        float4* s4p = (float4*)sp[buf];
        float4* s4t = (float4*)st[buf];
#pragma unroll
        for (int i = 0; i < 5; i++) {
            cp16(s4p + tid + i * TPB, gp + tid + i * TPB);
            cp16(s4t + tid + i * TPB, gt + tid + i * TPB);
        }
    };

    // ---- balanced contiguous chunk for this block ----
    const int b = blockIdx.x;
    const int base = NTILES / GRID;              // 12
    const int rem = NTILES % GRID;               // 112
    const int cnt = base + (b < rem ? 1 : 0);    // 12 or 13 tiles
    int tile = b * base + (b < rem ? b : rem);   // contiguous start

    float acc = 0.0f;
    int cur = 0;

    prefetch(0, tile);
    cp_commit();

    for (int k = 0; k < cnt; k++) {
        cp_wait0();           // this block's pending group (tile k) complete
        __syncthreads();      // async-proxy visibility + all threads done with
                              // the buffer about to be refilled
        if (k + 1 < cnt) {
            prefetch(cur ^ 1, tile + 1);         // overlap with compute below
            cp_commit();
        }

        // ---- per-cell loss: threads 0..63 compute (cell = tid) ----
        if (tid < TILE) {
            const float* p = sp[cur] + tid * 30;
            const float* t = st[cur] + tid * 30;

            const float coo = (t[4] > 0.0f) ? 1.0f : 0.0f;
            const float noo = 1.0f - coo;

            float d4 = p[4] - t[4];
            float d9 = p[9] - t[9];
            float loss = 0.5f * noo * (d4 * d4 + d9 * d9);

            float cls = 0.0f;
#pragma unroll
            for (int kk = 10; kk < 30; kk++) {
                float d = p[kk] - t[kk];
                cls += d * d;
            }
            loss += coo * cls;

            // degenerate IoU, matching the reference exactly:
            // inter = 1 iff (rb-lt)<0 in BOTH dims, else 0
            const float t_ltx = t[0] - 0.5f * t[2];
            const float t_lty = t[1] - 0.5f * t[3];
            const float t_rbx = t[0] + 0.5f * t[2];
            const float t_rby = t[1] + 0.5f * t[3];
            const float area2 = (t_rbx - t_ltx) * (t_rby - t_lty);

            float iou[2];
#pragma unroll
            for (int bb = 0; bb < 2; bb++) {
                const float* pb = p + bb * 5;
                float p_ltx = pb[0] - 0.5f * pb[2];
                float p_lty = pb[1] - 0.5f * pb[3];
                float p_rbx = pb[0] + 0.5f * pb[2];
                float p_rby = pb[1] + 0.5f * pb[3];
                float ltx = fmaxf(p_ltx, t_ltx);
                float lty = fmaxf(p_lty, t_lty);
                float rbx = fminf(p_rbx, t_rbx);
                float rby = fminf(p_rby, t_rby);
                float wh0 = (rbx - ltx < 0.0f) ? 1.0f : 0.0f;
                float wh1 = (rby - lty < 0.0f) ? 1.0f : 0.0f;
                float inter = wh0 * wh1;
                float area1 = (p_rbx - p_ltx) * (p_rby - p_lty);
                iou[bb] = inter / (area1 + area2 - inter);
            }
            const int idx = (iou[1] > iou[0]) ? 1 : 0;  // first index on ties
            const float* rp = p + idx * 5;
            const float* rt = t + idx * 5;

            float dc = rp[4] - rt[4];
            loss += coo * dc * dc;

            float dx = rp[0] - rt[0];
            float dy = rp[1] - rt[1];
            float wp2 = (coo > 0.0f) ? rp[2] : 1.0f;
            float wp3 = (coo > 0.0f) ? rp[3] : 1.0f;
            float wt2 = (coo > 0.0f) ? rt[2] : 1.0f;
            float wt3 = (coo > 0.0f) ? rt[3] : 1.0f;
            float dw = sqrtf(wp2) - sqrtf(wt2);
            float dh = sqrtf(wp3) - sqrtf(wt3);
            loss += 5.0f * coo * (dx * dx + dy * dy + dw * dw + dh * dh);

            acc += loss;
        }

        cur ^= 1;
        tile += 1;
        // no end barrier: buffer reuse is protected by the next
        // iteration's top barrier (prefetch is issued only after it)
    }

    // ---- block reduction (warp 2 holds acc=0) ----
#pragma unroll
    for (int o = 16; o > 0; o >>= 1)
        acc += __shfl_xor_sync(0xFFFFFFFFu, acc, o);
    if ((tid & 31) == 0)
        warpsum[tid >> 5] = acc;
    __syncthreads();

    if (tid == 0) {
        float s = warpsum[0] + warpsum[1] + warpsum[2];
        atomicAdd(&g_acc, (double)s * (1.0 / (double)N_BATCH));
        __threadfence();
        s_ticket = atomicAdd(&g_count, 1u);
    }
    __syncthreads();

    // ---- last block publishes scalar and resets state ----
    if (tid == 0 && s_ticket == GRID - 1) {
        double total = atomicAdd(&g_acc, 0.0);
        out[0] = (float)total;
        g_acc = 0.0;
        g_count = 0u;
    }
}

extern "C" void kernel_launch(void* const* d_in, const int* in_sizes, int n_in,
                              void* d_out, int out_size) {
    (void)in_sizes; (void)n_in; (void)out_size;
    const float* pred = (const float*)d_in[0];
    const float* targ = (const float*)d_in[1];
    float* out = (float*)d_out;

    yolo_loss_kernel<<<GRID, TPB>>>(pred, targ, out);
}